// round 12
// baseline (speedup 1.0000x reference)
#include <cuda_runtime.h>
#include <math.h>
#include <stdint.h>

// Problem constants (fixed by the dataset)
#define SD 5
#define OD 32
#define NB 256
#define TT 8192

// ---------------- scratch (device globals; allocation-free) ----------------
__device__ float g_proj[TT * 6 * NB];      // [(t*6+k)*NB+b]
__device__ float g_J[TT * 26];             // [t*26+e], e=25 -> logdetS
__device__ float g_U[25];
__device__ float g_llpart[NB * 256];       // [b][chunk]

// ---------------- Riccati config ----------------
#define R_LR 8
#define R_WR 24
#define R_NBLK 32                   // 1024 chunks

// ---------------- projection config (persistent, 3-stage ring, 2t tiles) ---
#define PP_NBLK 148                 // 1 block/SM
#define P_TPT 2                     // time steps per tile (contiguous in y)
#define NTILES (TT / P_TPT)         // 4096
#define TROWB 256                   // 2t x 32 floats per batch row
#define TILEB (NB * TROWB)          // 65536 B per tile
#define P_STAGES 3
#define P_SMEM (P_STAGES * TILEB)   // 196608 B ring

// ---------------- z-recursion + covs-broadcast config (R8-validated) -------
#define Z_L 32
#define Z_W 48
#define Z_NCHUNK (TT / Z_L)         // 256
#define Z_MAXSTEPS (Z_L + Z_W)      // 80
#define BC_TILE 32
#define BC_NBLK (TT / BC_TILE)      // 256
#define ZB_SMEM (Z_MAXSTEPS * 26 * 4 + NB * 41 * 4)   // 50304 B

// output offsets (tuple flattened: states, covs, ll)
#define OUT_STATES 0
#define OUT_COVS   ((size_t)NB * TT * SD)
#define OUT_LL     (OUT_COVS + (size_t)NB * TT * SD * SD)

// ============================================================================
// Kernel 1: data-independent Riccati recursion -> g_J, g_U
// ============================================================================
__global__ __launch_bounds__(32) void k_ricc(
    const float* __restrict__ Ain,
    const float* __restrict__ Cin,
    const float* __restrict__ Qlog,
    const float* __restrict__ Rlog)
{
    const int chunk = blockIdx.x * 32 + threadIdx.x;

    float a[25];
    #pragma unroll
    for (int i = 0; i < 25; i++) a[i] = Ain[i];
    float q[5];
    #pragma unroll
    for (int k = 0; k < 5; k++) q[k] = expf(Qlog[k]);

    float U[25];
    #pragma unroll
    for (int i = 0; i < 25; i++) U[i] = 0.f;
    float logdetR = 0.f;
    for (int o = 0; o < OD; o++) {
        float rl = Rlog[o];
        logdetR += rl;
        float ri = expf(-rl);
        float cv[5];
        #pragma unroll
        for (int k = 0; k < 5; k++) cv[k] = Cin[o * 5 + k];
        #pragma unroll
        for (int i = 0; i < 5; i++) {
            float f = ri * cv[i];
            #pragma unroll
            for (int j = 0; j < 5; j++) U[i * 5 + j] += f * cv[j];
        }
    }
    if (chunk == 0) {
        #pragma unroll
        for (int i = 0; i < 25; i++) g_U[i] = U[i];
    }

    const int town = chunk * R_LR;
    const int tend = town + R_LR;
    int t0s = town - R_WR; if (t0s < 0) t0s = 0;

    float P[25];
    #pragma unroll
    for (int i = 0; i < 25; i++) P[i] = (i % 6 == 0) ? 1.f : 0.f;

    for (int t = t0s; t < tend; ++t) {
        float Tm[25], Pp[25];
        #pragma unroll
        for (int i = 0; i < 5; i++)
            #pragma unroll
            for (int j = 0; j < 5; j++) {
                float s = 0.f;
                #pragma unroll
                for (int k = 0; k < 5; k++) s += a[i * 5 + k] * P[k * 5 + j];
                Tm[i * 5 + j] = s;
            }
        #pragma unroll
        for (int i = 0; i < 5; i++)
            #pragma unroll
            for (int j = 0; j < 5; j++) {
                float s = 0.f;
                #pragma unroll
                for (int k = 0; k < 5; k++) s += Tm[i * 5 + k] * a[j * 5 + k];
                Pp[i * 5 + j] = s;
            }
        #pragma unroll
        for (int i = 0; i < 5; i++) Pp[i * 5 + i] += q[i];

        float M[25], V[25];
        #pragma unroll
        for (int i = 0; i < 5; i++)
            #pragma unroll
            for (int j = 0; j < 5; j++) {
                float s = (i == j) ? 1.f : 0.f;
                #pragma unroll
                for (int k = 0; k < 5; k++) s += U[i * 5 + k] * Pp[k * 5 + j];
                M[i * 5 + j] = s;
            }
        #pragma unroll
        for (int i = 0; i < 25; i++) V[i] = (i % 6 == 0) ? 1.f : 0.f;
        float det = 1.f;
        #pragma unroll
        for (int k = 0; k < 5; k++) {
            float piv = M[k * 5 + k];
            det *= piv;
            float ip = 1.f / piv;
            #pragma unroll
            for (int j = 0; j < 5; j++) { M[k * 5 + j] *= ip; V[k * 5 + j] *= ip; }
            #pragma unroll
            for (int i2 = 0; i2 < 5; i2++) {
                if (i2 == k) continue;
                float f = M[i2 * 5 + k];
                #pragma unroll
                for (int j = 0; j < 5; j++) {
                    M[i2 * 5 + j] -= f * M[k * 5 + j];
                    V[i2 * 5 + j] -= f * V[k * 5 + j];
                }
            }
        }
        #pragma unroll
        for (int i = 0; i < 5; i++)
            #pragma unroll
            for (int j = 0; j < 5; j++) {
                float s = 0.f;
                #pragma unroll
                for (int k = 0; k < 5; k++) s += Pp[i * 5 + k] * V[k * 5 + j];
                P[i * 5 + j] = s;
            }

        if (t >= town) {
            float ld = logdetR + logf(det);
            #pragma unroll
            for (int e = 0; e < 25; e++) g_J[t * 26 + e] = P[e];
            g_J[t * 26 + 25] = ld;
        }
    }
}

// ---------------- cp.async helpers ----------------
__device__ __forceinline__ void cp16(uint32_t saddr, const void* gaddr) {
    asm volatile("cp.async.cg.shared.global [%0], [%1], 16;"
                 :: "r"(saddr), "l"(gaddr));
}
#define CP_COMMIT() asm volatile("cp.async.commit_group;" ::: "memory")
#define CP_WAIT2()  asm volatile("cp.async.wait_group 2;" ::: "memory")

// XOR swizzle: 16B chunk q (0..15) of row b goes to chunk q ^ (b & 7);
// low-3-bit XOR is a permutation over b mod 8 -> conflict-free LDS.128.
__device__ __forceinline__ uint32_t sw_off(int b, int q) {
    return (uint32_t)(b * TROWB + ((q ^ (b & 7)) << 4));
}

// ============================================================================
// Kernel 2: observation projection y -> g_proj
// 148 persistent blocks (1/SM), 3-stage ring of 64KB tiles (2 consecutive
// t's per batch row -> 256B contiguous DRAM bursts).
// ============================================================================
__global__ __launch_bounds__(256) void k_proj(
    const float* __restrict__ y,
    const float* __restrict__ Cin,
    const float* __restrict__ Rlog)
{
    extern __shared__ float sy[];            // [3][NB][64] swizzled stages
    __shared__ float pp[OD * 8];             // {crv0..4, rin, 0, 0} per o
    const int tid = threadIdx.x;

    if (tid < OD) {
        float ri = expf(-Rlog[tid]);
        #pragma unroll
        for (int k = 0; k < 5; k++) pp[tid * 8 + k] = Cin[tid * 5 + k] * ri;
        pp[tid * 8 + 5] = ri;
        pp[tid * 8 + 6] = 0.f;
        pp[tid * 8 + 7] = 0.f;
    }
    __syncthreads();

    const uint32_t sbase = (uint32_t)__cvta_generic_to_shared(sy);
    const char* yb = (const char*)y;
    const int bid = blockIdx.x;

    // prologue: tiles n=0,1 into stages 0,1
    #pragma unroll
    for (int d = 0; d < 2; ++d) {
        const int m = bid + d * PP_NBLK;
        if (m < NTILES) {
            #pragma unroll
            for (int it = 0; it < 16; ++it) {
                int f = it * 256 + tid;
                int b = f >> 4, q = f & 15;
                cp16(sbase + d * TILEB + sw_off(b, q),
                     yb + ((size_t)b * TT + (size_t)m * P_TPT) * 128 + q * 16);
            }
        }
        CP_COMMIT();
    }

    for (int n = 0;; ++n) {
        const int m = bid + n * PP_NBLK;
        if (m >= NTILES) break;

        // issue tile n+2 into stage (n+2)%3 (freed by barrier at end of n-1)
        const int mp = m + 2 * PP_NBLK;
        if (mp < NTILES) {
            const int sg = (n + 2) % 3;
            #pragma unroll
            for (int it = 0; it < 16; ++it) {
                int f = it * 256 + tid;
                int b = f >> 4, q = f & 15;
                cp16(sbase + sg * TILEB + sw_off(b, q),
                     yb + ((size_t)b * TT + (size_t)mp * P_TPT) * 128 + q * 16);
            }
        }
        CP_COMMIT();
        CP_WAIT2();            // tile n's group complete
        __syncthreads();

        // compute: thread = batch row b; two t's per tile
        const int b = tid;
        const char* base = (const char*)sy + (n % 3) * TILEB;
        const float4* p4 = (const float4*)pp;
        const int t0 = m * P_TPT;

        #pragma unroll
        for (int tt = 0; tt < P_TPT; ++tt) {
            float v[OD];
            #pragma unroll
            for (int q8 = 0; q8 < 8; q8++) {
                const float4 x =
                    *(const float4*)(base + sw_off(b, tt * 8 + q8));
                v[q8 * 4 + 0] = x.x; v[q8 * 4 + 1] = x.y;
                v[q8 * 4 + 2] = x.z; v[q8 * 4 + 3] = x.w;
            }
            float c0 = 0, c1 = 0, c2 = 0, c3 = 0, c4 = 0, syy = 0;
            #pragma unroll
            for (int o = 0; o < OD; o++) {
                float4 pa = p4[o * 2];
                float4 pb = p4[o * 2 + 1];
                float yv = v[o];
                c0 += pa.x * yv;
                c1 += pa.y * yv;
                c2 += pa.z * yv;
                c3 += pa.w * yv;
                c4 += pb.x * yv;
                syy += (pb.y * yv) * yv;
            }
            float* pd = &g_proj[((size_t)(t0 + tt) * 6) * NB + b];
            pd[0 * NB] = c0; pd[1 * NB] = c1; pd[2 * NB] = c2;
            pd[3 * NB] = c3; pd[4 * NB] = c4; pd[5 * NB] = syy;
        }

        __syncthreads();       // stage n reusable only after all reads done
    }
}

// ---------------- one z step ----------------
#define Z_STEP(CCBUF, U_)                                                     \
    {                                                                         \
        float zp[5];                                                          \
        _Pragma("unroll")                                                     \
        for (int i = 0; i < 5; i++)                                           \
            zp[i] = a[i*5+0]*z0 + a[i*5+1]*z1 + a[i*5+2]*z2                   \
                  + a[i*5+3]*z3 + a[i*5+4]*z4;                                \
        float g[5];                                                           \
        _Pragma("unroll")                                                     \
        for (int i = 0; i < 5; i++) {                                         \
            float sa = 0.f;                                                   \
            _Pragma("unroll")                                                 \
            for (int j = 0; j < 5; j++) sa += U_[i*5+j] * zp[j];              \
            g[i] = sa;                                                        \
        }                                                                     \
        float w[5];                                                           \
        _Pragma("unroll")                                                     \
        for (int i = 0; i < 5; i++) w[i] = (CCBUF)[i] - g[i];                 \
        const float* Jr = &sJ[s * 26];                                        \
        float h[5];                                                           \
        _Pragma("unroll")                                                     \
        for (int i = 0; i < 5; i++) {                                         \
            float sa = 0.f;                                                   \
            _Pragma("unroll")                                                 \
            for (int j = 0; j < 5; j++) sa += Jr[i*5+j] * w[j];               \
            h[i] = sa;                                                        \
        }                                                                     \
        z0 = zp[0]+h[0]; z1 = zp[1]+h[1]; z2 = zp[2]+h[2];                    \
        z3 = zp[3]+h[3]; z4 = zp[4]+h[4];                                     \
        if (s >= warm) {                                                      \
            float cz = 0, zg = 0, wh = 0;                                     \
            _Pragma("unroll")                                                 \
            for (int i = 0; i < 5; i++) {                                     \
                cz += (CCBUF)[i]*zp[i]; zg += zp[i]*g[i]; wh += w[i]*h[i];    \
            }                                                                 \
            float quad = (CCBUF)[5] - 2.f*cz + zg - wh;                       \
            ll -= 0.5f * ((float)OD * 1.8378770664093453f                     \
                          + Jr[25] + quad);                                   \
            int sl = (s - warm) & 7;                                          \
            float* sb = &sbuf[b * 41 + sl * 5];                               \
            sb[0]=z0; sb[1]=z1; sb[2]=z2; sb[3]=z3; sb[4]=z4;                 \
        }                                                                     \
    }

// ============================================================================
// Kernel 3: fused  (a) z-recursion + states + ll partials [blocks 0..255]
//                  (b) covariance broadcast J -> covs     [blocks 256..511]
// ============================================================================
__global__ __launch_bounds__(256) void k_zbc(
    const float* __restrict__ Ain, float* __restrict__ out)
{
    extern __shared__ float sm[];
    const int tid = threadIdx.x;

    if (blockIdx.x < Z_NCHUNK) {
        float* sJ   = sm;                         // [Z_MAXSTEPS][26]
        float* sbuf = sm + Z_MAXSTEPS * 26;       // [NB][41]

        const int chunk = blockIdx.x;
        const int town = chunk * Z_L;
        int t0 = town - Z_W; if (t0 < 0) t0 = 0;
        const int nsteps = town + Z_L - t0;       // 32 or 80 (both %8==0)
        const int warm = town - t0;               // 0 or 48

        for (int i = tid; i < nsteps * 26; i += 256) sJ[i] = g_J[t0 * 26 + i];
        __syncthreads();

        float a[25], U[25];
        #pragma unroll
        for (int i = 0; i < 25; i++) { a[i] = Ain[i]; U[i] = g_U[i]; }

        float z0 = 0, z1 = 0, z2 = 0, z3 = 0, z4 = 0;
        float ll = 0.f;
        const int b = tid;
        const float* pbase = &g_proj[(size_t)t0 * 6 * NB + b];

        float bufA[4][6], bufB[4][6];
        #pragma unroll
        for (int u = 0; u < 4; u++)
            #pragma unroll
            for (int k = 0; k < 6; k++)
                bufA[u][k] = pbase[((size_t)u * 6 + k) * NB];

        for (int s8 = 0; s8 < nsteps; s8 += 8) {
            if (s8 + 4 < nsteps) {
                const float* pn = pbase + (size_t)(s8 + 4) * 6 * NB;
                #pragma unroll
                for (int u = 0; u < 4; u++)
                    #pragma unroll
                    for (int k = 0; k < 6; k++)
                        bufB[u][k] = pn[((size_t)u * 6 + k) * NB];
            }
            #pragma unroll
            for (int u = 0; u < 4; u++) {
                const int s = s8 + u;
                Z_STEP(bufA[u], U)
            }
            if (s8 + 8 < nsteps) {
                const float* pn = pbase + (size_t)(s8 + 8) * 6 * NB;
                #pragma unroll
                for (int u = 0; u < 4; u++)
                    #pragma unroll
                    for (int k = 0; k < 6; k++)
                        bufA[u][k] = pn[((size_t)u * 6 + k) * NB];
            }
            #pragma unroll
            for (int u = 0; u < 4; u++) {
                const int s = s8 + 4 + u;
                Z_STEP(bufB[u], U)
            }
            if (s8 >= warm) {
                __syncthreads();
                const int tflush0 = town + (s8 - warm);
                for (int f = tid; f < NB * 40; f += 256) {
                    int bb = f / 40;
                    int u  = f % 40;
                    __stcs(&out[OUT_STATES + ((size_t)bb * TT + tflush0) * 5 + u],
                           sbuf[bb * 41 + u]);
                }
                __syncthreads();
            }
        }
        g_llpart[(size_t)b * Z_NCHUNK + chunk] = ll;
    } else {
        // ---- covariance broadcast: contiguous float4 streaming stores ----
        const int v = blockIdx.x - Z_NCHUNK;       // 0..255
        const int t0 = v * BC_TILE;
        float* sJ = sm;                            // 800 floats
        for (int i = tid; i < BC_TILE * 25; i += 256) {
            int tt = i / 25;
            int e  = i % 25;
            sJ[i] = g_J[(t0 + tt) * 26 + e];
        }
        __syncthreads();
        const float4* sJ4 = (const float4*)sJ;     // 200 float4
        float4* out4 = (float4*)(out + OUT_COVS);
        const unsigned base = (unsigned)v * 200u;
        if (tid < 200) {
            float4 val = sJ4[tid];
            #pragma unroll 4
            for (int bb = 0; bb < NB; ++bb) {
                __stcs(&out4[(size_t)bb * (TT * 25 / 4) + base + tid], val);
            }
        }
    }
}

// ============================================================================
// Kernel 4: ll reduction — block = one batch, 32 lanes, butterfly reduce
// ============================================================================
__global__ __launch_bounds__(32) void k_ll(float* __restrict__ out)
{
    const int b = blockIdx.x;
    const int lane = threadIdx.x;
    const float* p = &g_llpart[(size_t)b * Z_NCHUNK];
    float s = 0.f;
    #pragma unroll
    for (int k = 0; k < Z_NCHUNK / 32; k++) s += p[lane + k * 32];
    #pragma unroll
    for (int d = 16; d >= 1; d >>= 1)
        s += __shfl_xor_sync(0xFFFFFFFFu, s, d);
    if (lane == 0) out[OUT_LL + b] = s;
}

// ============================================================================
extern "C" void kernel_launch(void* const* d_in, const int* in_sizes, int n_in,
                              void* d_out, int out_size)
{
    const float* y  = (const float*)d_in[0];
    const float* A  = (const float*)d_in[1];
    const float* C  = (const float*)d_in[2];
    const float* Ql = (const float*)d_in[3];
    const float* Rl = (const float*)d_in[4];
    float* out = (float*)d_out;

    cudaFuncSetAttribute(k_proj, cudaFuncAttributeMaxDynamicSharedMemorySize, P_SMEM);
    cudaFuncSetAttribute(k_zbc, cudaFuncAttributeMaxDynamicSharedMemorySize, ZB_SMEM);

    k_ricc<<<R_NBLK, 32>>>(A, C, Ql, Rl);
    k_proj<<<PP_NBLK, 256, P_SMEM>>>(y, C, Rl);
    k_zbc<<<Z_NCHUNK + BC_NBLK, 256, ZB_SMEM>>>(A, out);
    k_ll<<<NB, 32>>>(out);
}

// round 13
// speedup vs baseline: 1.0389x; 1.0389x over previous
#include <cuda_runtime.h>
#include <math.h>
#include <stdint.h>

// Problem constants (fixed by the dataset)
#define SD 5
#define OD 32
#define NB 256
#define TT 8192

// ---------------- scratch (device globals; allocation-free) ----------------
__device__ float g_proj[TT * 6 * NB];      // [(t*6+k)*NB+b]
__device__ float g_J[TT * 26];             // [t*26+e], e=25 -> logdetS
__device__ float g_U[25];
__device__ float g_llpart[NB * 256];       // [b][chunk]

// ---------------- Riccati config ----------------
#define R_LR 8
#define R_WR 24
#define R_NBLK 32                   // 1024 chunks

// ---------------- projection config (persistent, 3-stage ring, 2t tiles) ---
#define PP_NBLK 148                 // 1 block/SM
#define P_TPT 2                     // time steps per tile (contiguous in y)
#define NTILES (TT / P_TPT)         // 4096
#define TROWB 256                   // 2t x 32 floats per batch row
#define TILEB (NB * TROWB)          // 65536 B per tile
#define P_STAGES 3
#define P_SMEM (P_STAGES * TILEB)   // 196608 B ring

// ---------------- z-recursion + covs-broadcast config (R8-validated) -------
#define Z_L 32
#define Z_W 48
#define Z_NCHUNK (TT / Z_L)         // 256
#define Z_MAXSTEPS (Z_L + Z_W)      // 80
#define BC_TILE 32
#define BC_NBLK (TT / BC_TILE)      // 256
#define ZB_SMEM (Z_MAXSTEPS * 26 * 4 + NB * 41 * 4)   // 50304 B

// output offsets (tuple flattened: states, covs, ll)
#define OUT_STATES 0
#define OUT_COVS   ((size_t)NB * TT * SD)
#define OUT_LL     (OUT_COVS + (size_t)NB * TT * SD * SD)

// ============================================================================
// Kernel 1: data-independent Riccati recursion -> g_J, g_U
// ============================================================================
__global__ __launch_bounds__(32) void k_ricc(
    const float* __restrict__ Ain,
    const float* __restrict__ Cin,
    const float* __restrict__ Qlog,
    const float* __restrict__ Rlog)
{
    const int chunk = blockIdx.x * 32 + threadIdx.x;

    float a[25];
    #pragma unroll
    for (int i = 0; i < 25; i++) a[i] = Ain[i];
    float q[5];
    #pragma unroll
    for (int k = 0; k < 5; k++) q[k] = expf(Qlog[k]);

    float U[25];
    #pragma unroll
    for (int i = 0; i < 25; i++) U[i] = 0.f;
    float logdetR = 0.f;
    for (int o = 0; o < OD; o++) {
        float rl = Rlog[o];
        logdetR += rl;
        float ri = expf(-rl);
        float cv[5];
        #pragma unroll
        for (int k = 0; k < 5; k++) cv[k] = Cin[o * 5 + k];
        #pragma unroll
        for (int i = 0; i < 5; i++) {
            float f = ri * cv[i];
            #pragma unroll
            for (int j = 0; j < 5; j++) U[i * 5 + j] += f * cv[j];
        }
    }
    if (chunk == 0) {
        #pragma unroll
        for (int i = 0; i < 25; i++) g_U[i] = U[i];
    }

    const int town = chunk * R_LR;
    const int tend = town + R_LR;
    int t0s = town - R_WR; if (t0s < 0) t0s = 0;

    float P[25];
    #pragma unroll
    for (int i = 0; i < 25; i++) P[i] = (i % 6 == 0) ? 1.f : 0.f;

    for (int t = t0s; t < tend; ++t) {
        float Tm[25], Pp[25];
        #pragma unroll
        for (int i = 0; i < 5; i++)
            #pragma unroll
            for (int j = 0; j < 5; j++) {
                float s = 0.f;
                #pragma unroll
                for (int k = 0; k < 5; k++) s += a[i * 5 + k] * P[k * 5 + j];
                Tm[i * 5 + j] = s;
            }
        #pragma unroll
        for (int i = 0; i < 5; i++)
            #pragma unroll
            for (int j = 0; j < 5; j++) {
                float s = 0.f;
                #pragma unroll
                for (int k = 0; k < 5; k++) s += Tm[i * 5 + k] * a[j * 5 + k];
                Pp[i * 5 + j] = s;
            }
        #pragma unroll
        for (int i = 0; i < 5; i++) Pp[i * 5 + i] += q[i];

        float M[25], V[25];
        #pragma unroll
        for (int i = 0; i < 5; i++)
            #pragma unroll
            for (int j = 0; j < 5; j++) {
                float s = (i == j) ? 1.f : 0.f;
                #pragma unroll
                for (int k = 0; k < 5; k++) s += U[i * 5 + k] * Pp[k * 5 + j];
                M[i * 5 + j] = s;
            }
        #pragma unroll
        for (int i = 0; i < 25; i++) V[i] = (i % 6 == 0) ? 1.f : 0.f;
        float det = 1.f;
        #pragma unroll
        for (int k = 0; k < 5; k++) {
            float piv = M[k * 5 + k];
            det *= piv;
            float ip = 1.f / piv;
            #pragma unroll
            for (int j = 0; j < 5; j++) { M[k * 5 + j] *= ip; V[k * 5 + j] *= ip; }
            #pragma unroll
            for (int i2 = 0; i2 < 5; i2++) {
                if (i2 == k) continue;
                float f = M[i2 * 5 + k];
                #pragma unroll
                for (int j = 0; j < 5; j++) {
                    M[i2 * 5 + j] -= f * M[k * 5 + j];
                    V[i2 * 5 + j] -= f * V[k * 5 + j];
                }
            }
        }
        #pragma unroll
        for (int i = 0; i < 5; i++)
            #pragma unroll
            for (int j = 0; j < 5; j++) {
                float s = 0.f;
                #pragma unroll
                for (int k = 0; k < 5; k++) s += Pp[i * 5 + k] * V[k * 5 + j];
                P[i * 5 + j] = s;
            }

        if (t >= town) {
            float ld = logdetR + logf(det);
            #pragma unroll
            for (int e = 0; e < 25; e++) g_J[t * 26 + e] = P[e];
            g_J[t * 26 + 25] = ld;
        }
    }
}

// ---------------- cp.async + cache-policy helpers ----------------
__device__ __forceinline__ uint64_t mk_evict_first() {
    uint64_t p;
    asm("createpolicy.fractional.L2::evict_first.b64 %0, 1.0;" : "=l"(p));
    return p;
}
__device__ __forceinline__ uint64_t mk_evict_last() {
    uint64_t p;
    asm("createpolicy.fractional.L2::evict_last.b64 %0, 1.0;" : "=l"(p));
    return p;
}
// y load: evict_first (single-use stream; don't pollute L2)
__device__ __forceinline__ void cp16_ef(uint32_t saddr, const void* gaddr,
                                        uint64_t pol) {
    asm volatile("cp.async.cg.shared.global.L2::cache_hint [%0], [%1], 16, %2;"
                 :: "r"(saddr), "l"(gaddr), "l"(pol));
}
// proj store: evict_last (pin the 50MB proj buffer in L2 for k_zbc)
__device__ __forceinline__ void st_el(float* p, float v, uint64_t pol) {
    asm volatile("st.global.L2::cache_hint.f32 [%0], %2, %1;"
                 :: "l"(p), "l"(pol), "f"(v));
}
#define CP_COMMIT() asm volatile("cp.async.commit_group;" ::: "memory")
#define CP_WAIT2()  asm volatile("cp.async.wait_group 2;" ::: "memory")

// XOR swizzle: 16B chunk q (0..15) of row b goes to chunk q ^ (b & 7)
__device__ __forceinline__ uint32_t sw_off(int b, int q) {
    return (uint32_t)(b * TROWB + ((q ^ (b & 7)) << 4));
}

// ============================================================================
// Kernel 2: observation projection y -> g_proj
// 148 persistent blocks (1/SM), 3-stage ring of 64KB tiles (2 t's per row).
// y streamed evict_first; proj written evict_last (stays L2-resident).
// ============================================================================
__global__ __launch_bounds__(256) void k_proj(
    const float* __restrict__ y,
    const float* __restrict__ Cin,
    const float* __restrict__ Rlog)
{
    extern __shared__ float sy[];            // [3][NB][64] swizzled stages
    __shared__ float pp[OD * 8];             // {crv0..4, rin, 0, 0} per o
    const int tid = threadIdx.x;

    if (tid < OD) {
        float ri = expf(-Rlog[tid]);
        #pragma unroll
        for (int k = 0; k < 5; k++) pp[tid * 8 + k] = Cin[tid * 5 + k] * ri;
        pp[tid * 8 + 5] = ri;
        pp[tid * 8 + 6] = 0.f;
        pp[tid * 8 + 7] = 0.f;
    }
    __syncthreads();

    const uint64_t pol_ef = mk_evict_first();
    const uint64_t pol_el = mk_evict_last();
    const uint32_t sbase = (uint32_t)__cvta_generic_to_shared(sy);
    const char* yb = (const char*)y;
    const int bid = blockIdx.x;

    // prologue: tiles n=0,1 into stages 0,1
    #pragma unroll
    for (int d = 0; d < 2; ++d) {
        const int m = bid + d * PP_NBLK;
        if (m < NTILES) {
            #pragma unroll
            for (int it = 0; it < 16; ++it) {
                int f = it * 256 + tid;
                int b = f >> 4, q = f & 15;
                cp16_ef(sbase + d * TILEB + sw_off(b, q),
                        yb + ((size_t)b * TT + (size_t)m * P_TPT) * 128 + q * 16,
                        pol_ef);
            }
        }
        CP_COMMIT();
    }

    for (int n = 0;; ++n) {
        const int m = bid + n * PP_NBLK;
        if (m >= NTILES) break;

        const int mp = m + 2 * PP_NBLK;
        if (mp < NTILES) {
            const int sg = (n + 2) % 3;
            #pragma unroll
            for (int it = 0; it < 16; ++it) {
                int f = it * 256 + tid;
                int b = f >> 4, q = f & 15;
                cp16_ef(sbase + sg * TILEB + sw_off(b, q),
                        yb + ((size_t)b * TT + (size_t)mp * P_TPT) * 128 + q * 16,
                        pol_ef);
            }
        }
        CP_COMMIT();
        CP_WAIT2();            // tile n's group complete
        __syncthreads();

        // compute: thread = batch row b; two t's per tile
        const int b = tid;
        const char* base = (const char*)sy + (n % 3) * TILEB;
        const float4* p4 = (const float4*)pp;
        const int t0 = m * P_TPT;

        #pragma unroll
        for (int tt = 0; tt < P_TPT; ++tt) {
            float v[OD];
            #pragma unroll
            for (int q8 = 0; q8 < 8; q8++) {
                const float4 x =
                    *(const float4*)(base + sw_off(b, tt * 8 + q8));
                v[q8 * 4 + 0] = x.x; v[q8 * 4 + 1] = x.y;
                v[q8 * 4 + 2] = x.z; v[q8 * 4 + 3] = x.w;
            }
            float c0 = 0, c1 = 0, c2 = 0, c3 = 0, c4 = 0, syy = 0;
            #pragma unroll
            for (int o = 0; o < OD; o++) {
                float4 pa = p4[o * 2];
                float4 pb = p4[o * 2 + 1];
                float yv = v[o];
                c0 += pa.x * yv;
                c1 += pa.y * yv;
                c2 += pa.z * yv;
                c3 += pa.w * yv;
                c4 += pb.x * yv;
                syy += (pb.y * yv) * yv;
            }
            float* pd = &g_proj[((size_t)(t0 + tt) * 6) * NB + b];
            st_el(pd + 0 * NB, c0, pol_el);
            st_el(pd + 1 * NB, c1, pol_el);
            st_el(pd + 2 * NB, c2, pol_el);
            st_el(pd + 3 * NB, c3, pol_el);
            st_el(pd + 4 * NB, c4, pol_el);
            st_el(pd + 5 * NB, syy, pol_el);
        }

        __syncthreads();       // stage n reusable only after all reads done
    }
}

// ---------------- one z step ----------------
#define Z_STEP(CCBUF, U_)                                                     \
    {                                                                         \
        float zp[5];                                                          \
        _Pragma("unroll")                                                     \
        for (int i = 0; i < 5; i++)                                           \
            zp[i] = a[i*5+0]*z0 + a[i*5+1]*z1 + a[i*5+2]*z2                   \
                  + a[i*5+3]*z3 + a[i*5+4]*z4;                                \
        float g[5];                                                           \
        _Pragma("unroll")                                                     \
        for (int i = 0; i < 5; i++) {                                         \
            float sa = 0.f;                                                   \
            _Pragma("unroll")                                                 \
            for (int j = 0; j < 5; j++) sa += U_[i*5+j] * zp[j];              \
            g[i] = sa;                                                        \
        }                                                                     \
        float w[5];                                                           \
        _Pragma("unroll")                                                     \
        for (int i = 0; i < 5; i++) w[i] = (CCBUF)[i] - g[i];                 \
        const float* Jr = &sJ[s * 26];                                        \
        float h[5];                                                           \
        _Pragma("unroll")                                                     \
        for (int i = 0; i < 5; i++) {                                         \
            float sa = 0.f;                                                   \
            _Pragma("unroll")                                                 \
            for (int j = 0; j < 5; j++) sa += Jr[i*5+j] * w[j];               \
            h[i] = sa;                                                        \
        }                                                                     \
        z0 = zp[0]+h[0]; z1 = zp[1]+h[1]; z2 = zp[2]+h[2];                    \
        z3 = zp[3]+h[3]; z4 = zp[4]+h[4];                                     \
        if (s >= warm) {                                                      \
            float cz = 0, zg = 0, wh = 0;                                     \
            _Pragma("unroll")                                                 \
            for (int i = 0; i < 5; i++) {                                     \
                cz += (CCBUF)[i]*zp[i]; zg += zp[i]*g[i]; wh += w[i]*h[i];    \
            }                                                                 \
            float quad = (CCBUF)[5] - 2.f*cz + zg - wh;                       \
            ll -= 0.5f * ((float)OD * 1.8378770664093453f                     \
                          + Jr[25] + quad);                                   \
            int sl = (s - warm) & 7;                                          \
            float* sb = &sbuf[b * 41 + sl * 5];                               \
            sb[0]=z0; sb[1]=z1; sb[2]=z2; sb[3]=z3; sb[4]=z4;                 \
        }                                                                     \
    }

// ============================================================================
// Kernel 3: fused  (a) z-recursion + states + ll partials [blocks 0..255]
//                  (b) covariance broadcast J -> covs     [blocks 256..511]
// proj reads via __ldcs (L2 hit expected, then evict — line is dead).
// ============================================================================
__global__ __launch_bounds__(256) void k_zbc(
    const float* __restrict__ Ain, float* __restrict__ out)
{
    extern __shared__ float sm[];
    const int tid = threadIdx.x;

    if (blockIdx.x < Z_NCHUNK) {
        float* sJ   = sm;                         // [Z_MAXSTEPS][26]
        float* sbuf = sm + Z_MAXSTEPS * 26;       // [NB][41]

        const int chunk = blockIdx.x;
        const int town = chunk * Z_L;
        int t0 = town - Z_W; if (t0 < 0) t0 = 0;
        const int nsteps = town + Z_L - t0;       // 32 or 80 (both %8==0)
        const int warm = town - t0;               // 0 or 48

        for (int i = tid; i < nsteps * 26; i += 256) sJ[i] = g_J[t0 * 26 + i];
        __syncthreads();

        float a[25], U[25];
        #pragma unroll
        for (int i = 0; i < 25; i++) { a[i] = Ain[i]; U[i] = g_U[i]; }

        float z0 = 0, z1 = 0, z2 = 0, z3 = 0, z4 = 0;
        float ll = 0.f;
        const int b = tid;
        const float* pbase = &g_proj[(size_t)t0 * 6 * NB + b];

        float bufA[4][6], bufB[4][6];
        #pragma unroll
        for (int u = 0; u < 4; u++)
            #pragma unroll
            for (int k = 0; k < 6; k++)
                bufA[u][k] = __ldcs(&pbase[((size_t)u * 6 + k) * NB]);

        for (int s8 = 0; s8 < nsteps; s8 += 8) {
            if (s8 + 4 < nsteps) {
                const float* pn = pbase + (size_t)(s8 + 4) * 6 * NB;
                #pragma unroll
                for (int u = 0; u < 4; u++)
                    #pragma unroll
                    for (int k = 0; k < 6; k++)
                        bufB[u][k] = __ldcs(&pn[((size_t)u * 6 + k) * NB]);
            }
            #pragma unroll
            for (int u = 0; u < 4; u++) {
                const int s = s8 + u;
                Z_STEP(bufA[u], U)
            }
            if (s8 + 8 < nsteps) {
                const float* pn = pbase + (size_t)(s8 + 8) * 6 * NB;
                #pragma unroll
                for (int u = 0; u < 4; u++)
                    #pragma unroll
                    for (int k = 0; k < 6; k++)
                        bufA[u][k] = __ldcs(&pn[((size_t)u * 6 + k) * NB]);
            }
            #pragma unroll
            for (int u = 0; u < 4; u++) {
                const int s = s8 + 4 + u;
                Z_STEP(bufB[u], U)
            }
            if (s8 >= warm) {
                __syncthreads();
                const int tflush0 = town + (s8 - warm);
                for (int f = tid; f < NB * 40; f += 256) {
                    int bb = f / 40;
                    int u  = f % 40;
                    __stcs(&out[OUT_STATES + ((size_t)bb * TT + tflush0) * 5 + u],
                           sbuf[bb * 41 + u]);
                }
                __syncthreads();
            }
        }
        g_llpart[(size_t)b * Z_NCHUNK + chunk] = ll;
    } else {
        // ---- covariance broadcast: contiguous float4 streaming stores ----
        const int v = blockIdx.x - Z_NCHUNK;       // 0..255
        const int t0 = v * BC_TILE;
        float* sJ = sm;                            // 800 floats
        for (int i = tid; i < BC_TILE * 25; i += 256) {
            int tt = i / 25;
            int e  = i % 25;
            sJ[i] = g_J[(t0 + tt) * 26 + e];
        }
        __syncthreads();
        const float4* sJ4 = (const float4*)sJ;     // 200 float4
        float4* out4 = (float4*)(out + OUT_COVS);
        const unsigned base = (unsigned)v * 200u;
        if (tid < 200) {
            float4 val = sJ4[tid];
            #pragma unroll 4
            for (int bb = 0; bb < NB; ++bb) {
                __stcs(&out4[(size_t)bb * (TT * 25 / 4) + base + tid], val);
            }
        }
    }
}

// ============================================================================
// Kernel 4: ll reduction — block = one batch, 32 lanes, butterfly reduce
// ============================================================================
__global__ __launch_bounds__(32) void k_ll(float* __restrict__ out)
{
    const int b = blockIdx.x;
    const int lane = threadIdx.x;
    const float* p = &g_llpart[(size_t)b * Z_NCHUNK];
    float s = 0.f;
    #pragma unroll
    for (int k = 0; k < Z_NCHUNK / 32; k++) s += p[lane + k * 32];
    #pragma unroll
    for (int d = 16; d >= 1; d >>= 1)
        s += __shfl_xor_sync(0xFFFFFFFFu, s, d);
    if (lane == 0) out[OUT_LL + b] = s;
}

// ============================================================================
extern "C" void kernel_launch(void* const* d_in, const int* in_sizes, int n_in,
                              void* d_out, int out_size)
{
    const float* y  = (const float*)d_in[0];
    const float* A  = (const float*)d_in[1];
    const float* C  = (const float*)d_in[2];
    const float* Ql = (const float*)d_in[3];
    const float* Rl = (const float*)d_in[4];
    float* out = (float*)d_out;

    cudaFuncSetAttribute(k_proj, cudaFuncAttributeMaxDynamicSharedMemorySize, P_SMEM);
    cudaFuncSetAttribute(k_zbc, cudaFuncAttributeMaxDynamicSharedMemorySize, ZB_SMEM);

    k_ricc<<<R_NBLK, 32>>>(A, C, Ql, Rl);
    k_proj<<<PP_NBLK, 256, P_SMEM>>>(y, C, Rl);
    k_zbc<<<Z_NCHUNK + BC_NBLK, 256, ZB_SMEM>>>(A, out);
    k_ll<<<NB, 32>>>(out);
}